// round 7
// baseline (speedup 1.0000x reference)
#include <cuda_runtime.h>
#include <cstdint>

// ---------------- problem constants ----------------
#define BB   32
#define CI_  128
#define CO_  128
#define HH   56
#define WW   56
#define HW   3136          // 56*56
#define PADW 58            // padded x
#define PADH 60            // padded y (extra 2 rows for tail-tile garbage reads)

#define MTILE 128          // flattened pixels per CTA
#define NTILES 25          // ceil(3136/128) (tail half-masked)

#define AROWS 348          // 6 halo rows x 58 cols (tiles can span 4 image rows)
#define ABYTES (AROWS * 128)        // 44544
#define BBYTES (CO_ * 128)          // 16384 per buffer
#define SMEM_CONV (ABYTES + 2 * BBYTES)   // 77312

// ---------------- scratch (device globals; no runtime alloc) ----------------
// both stored PRE-ROUNDED to tf32 bit patterns
__device__ float g_W2 [(size_t)BB * 9 * CO_ * CI_];        // [b][tap][co][ci]
__device__ float g_pad[(size_t)BB * PADH * PADW * CI_];    // [b][y][x][ci]

// ---------------- helpers ----------------
__device__ __forceinline__ uint32_t smem_to_u32(const void* p) {
    uint32_t a;
    asm("{ .reg .u64 t; cvta.to.shared.u64 t, %1; cvt.u32.u64 %0, t; }" : "=r"(a) : "l"(p));
    return a;
}
__device__ __forceinline__ uint32_t f32_to_tf32(float f) {
    uint32_t r; asm("cvt.rna.tf32.f32 %0, %1;" : "=r"(r) : "f"(f)); return r;
}
__device__ __forceinline__ void ldsm_x4(uint32_t* r, uint32_t addr) {
    asm volatile("ldmatrix.sync.aligned.m8n8.x4.shared.b16 {%0,%1,%2,%3}, [%4];"
        : "=r"(r[0]), "=r"(r[1]), "=r"(r[2]), "=r"(r[3]) : "r"(addr));
}
__device__ __forceinline__ void mma_tf32(float* c, const uint32_t* a, const uint32_t* b) {
    asm volatile("mma.sync.aligned.m16n8k8.row.col.f32.tf32.tf32.f32 "
        "{%0,%1,%2,%3}, {%4,%5,%6,%7}, {%8,%9}, {%0,%1,%2,%3};"
        : "+f"(c[0]), "+f"(c[1]), "+f"(c[2]), "+f"(c[3])
        : "r"(a[0]), "r"(a[1]), "r"(a[2]), "r"(a[3]), "r"(b[0]), "r"(b[1]));
}
__device__ __forceinline__ void cp16(uint32_t dst, const void* src) {
    asm volatile("cp.async.cg.shared.global [%0], [%1], 16;" :: "r"(dst), "l"(src));
}
#define CP_COMMIT() asm volatile("cp.async.commit_group;" ::: "memory")
#define CP_WAIT0()  asm volatile("cp.async.wait_group 0;" ::: "memory")

// ---------------------------------------------------------------------------
// prep W (fused): g_W2[b][tap][co][ci] = tf32(eps[b][co][ci*9+tap]*exp(psi)+mu)
// ---------------------------------------------------------------------------
__global__ void prepw_kernel(const float* __restrict__ eps,
                             const float* __restrict__ psi,
                             const float* __restrict__ mu) {
    int ci = threadIdx.x;
    int co = blockIdx.x, b = blockIdx.y;
    const float* e = eps + ((size_t)(b * CO_ + co) * CI_ + ci) * 9;
    const float* p = psi + ((size_t)co * CI_ + ci) * 9;
    const float* m = mu  + ((size_t)co * CI_ + ci) * 9;
    float v[9];
#pragma unroll
    for (int k = 0; k < 9; k++)
        v[k] = fmaf(e[k], __expf(p[k]), m[k]);
#pragma unroll
    for (int k = 0; k < 9; k++)
        g_W2[((size_t)(b * 9 + k) * CO_ + co) * CI_ + ci] = __uint_as_float(f32_to_tf32(v[k]));
}

// ---------------------------------------------------------------------------
// zero pad borders: rows 0,57,58,59 full + cols 0,57 of rows 1..56
// ---------------------------------------------------------------------------
__global__ void zeroborder_kernel() {
    int gi = blockIdx.x * 256 + threadIdx.x;
    if (gi >= BB * 344 * 32) return;
    int b = gi / (344 * 32);
    int r = gi % (344 * 32);
    int pi = r >> 5, f = r & 31;
    int y, x;
    if (pi < 58)       { y = 0;  x = pi; }
    else if (pi < 116) { y = 57; x = pi - 58; }
    else if (pi < 174) { y = 58; x = pi - 116; }
    else if (pi < 232) { y = 59; x = pi - 174; }
    else if (pi < 288) { y = pi - 232 + 1; x = 0; }
    else               { y = pi - 288 + 1; x = 57; }
    ((float4*)g_pad)[(((size_t)b * PADH + y) * PADW + x) * 32 + f] = make_float4(0.f, 0.f, 0.f, 0.f);
}

// ---------------------------------------------------------------------------
// NCHW -> padded NHWC, pre-rounded to tf32
// ---------------------------------------------------------------------------
__global__ void intrans_kernel(const float* __restrict__ in) {
    __shared__ float t[32][33];
    int b = blockIdx.z, hw0 = blockIdx.x * 32, ci0 = blockIdx.y * 32;
    int tx = threadIdx.x, ty = threadIdx.y;
    const float* ib = in + (size_t)b * CI_ * HW;
#pragma unroll
    for (int j = 0; j < 32; j += 8)
        t[ty + j][tx] = ib[(size_t)(ci0 + ty + j) * HW + hw0 + tx];
    __syncthreads();
#pragma unroll
    for (int j = 0; j < 32; j += 8) {
        int hw = hw0 + ty + j;
        int y = hw / WW, x = hw - y * WW;
        g_pad[(((size_t)b * PADH + y + 1) * PADW + (x + 1)) * CI_ + ci0 + tx] =
            __uint_as_float(f32_to_tf32(t[tx][ty + j]));
    }
}

// ---------------------------------------------------------------------------
// conv: implicit GEMM, mma.sync tf32, cp.async staging.
// CTA = 128 flattened pixels x 128 co. Warp grid 2(M) x 4(N):
//   warp = 4 m-frags x 32 co  (LDSM:MMA = 6:16 per kk).
// A staged once per ci-chunk over a 6-row x 58-col halo (tiles may span 4
// image rows); 9 taps read at row offset u*58+v. B double-buffered per tap.
// grid (25, 32), block 256.
// ---------------------------------------------------------------------------
__global__ __launch_bounds__(256, 2) void conv_mma(float* __restrict__ out) {
    extern __shared__ __align__(128) char smem[];
    uint32_t As_u = smem_to_u32(smem);
    uint32_t Bs_u = As_u + ABYTES;

    int tid = threadIdx.x, lid = tid & 31, wid = tid >> 5;
    int tile = blockIdx.x, b = blockIdx.y;
    int m_w = wid >> 2;                 // 0..1  (M half)
    int n_w = wid & 3;                  // 0..3  (N quarter)

    int p0   = tile * MTILE;
    int y_lo = p0 / WW;

    const float* apage = g_pad + (((size_t)b * PADH + y_lo) * PADW) * CI_;
    const float* wpage = g_W2 + (size_t)b * 9 * CO_ * CI_;

    // ---- fragment lane addressing ----
    int rA    = lid & 7;
    int add8A = ((lid >> 3) & 1) << 3;
    int jAh   = lid >> 4;               // A k-block half
    int jBh   = (lid >> 3) & 1;         // B k-block half
    int rowB  = n_w * 32 + (((lid >> 4) & 1) << 3) + rA;
    uint32_t b_base  = Bs_u + (uint32_t)rowB * 128;
    uint32_t xorB_sh = (uint32_t)rA << 4;

    // per-lane pixel -> halo-row base for this warp's 4 m-frags (u=0,v=0)
    int row_pq[4];
#pragma unroll
    for (int mf = 0; mf < 4; mf++) {
        int p  = p0 + (m_w * 4 + mf) * 16 + rA + add8A;
        int y  = p / WW;
        row_pq[mf] = (y - y_lo) * PADW + (p - y * WW);
    }

    float acc[4][4][4];
#pragma unroll
    for (int mf = 0; mf < 4; mf++)
#pragma unroll
        for (int nn = 0; nn < 4; nn++)
#pragma unroll
            for (int q = 0; q < 4; q++) acc[mf][nn][q] = 0.f;

    int buf = 0;
    for (int cc = 0; cc < 4; cc++) {
        int ccol = cc * 32;
        __syncthreads();   // previous-cc reads of As / Bs done

        // ---- stage A: 348 rows x 8 x 16B = 2784 cp16, swizzled ----
#pragma unroll
        for (int t = 0; t < 11; t++) {
            int c = tid + t * 256;
            if (t < 10 || c < AROWS * 8) {
                int q = c >> 3, j = c & 7;
                cp16(As_u + (uint32_t)(q * 128 + ((j ^ (q & 7)) << 4)),
                     apage + (size_t)q * CI_ + ccol + j * 4);
            }
        }
        // ---- stage B tap 0 into buf ----
        {
            const float* wsrc = wpage + ccol;
#pragma unroll
            for (int t = 0; t < 4; t++) {
                int c = tid + t * 256;
                int co = c >> 3, j = c & 7;
                cp16(Bs_u + (uint32_t)(buf * BBYTES + co * 128 + ((j ^ (co & 7)) << 4)),
                     wsrc + (size_t)co * CI_ + j * 4);
            }
        }
        CP_COMMIT();

        for (int uv = 0; uv < 9; uv++) {
            CP_WAIT0();
            __syncthreads();

            if (uv < 8) {   // prefetch next tap's B into other buffer
                const float* wsrc = wpage + (size_t)(uv + 1) * CO_ * CI_ + ccol;
#pragma unroll
                for (int t = 0; t < 4; t++) {
                    int c = tid + t * 256;
                    int co = c >> 3, j = c & 7;
                    cp16(Bs_u + (uint32_t)((buf ^ 1) * BBYTES + co * 128 + ((j ^ (co & 7)) << 4)),
                         wsrc + (size_t)co * CI_ + j * 4);
                }
                CP_COMMIT();
            }

            // ---- compute tap uv ----
            int u = uv / 3, v = uv - u * 3;
            int du = u * PADW + v;
            uint32_t abase[4], axsh[4];
#pragma unroll
            for (int mf = 0; mf < 4; mf++) {
                int q = row_pq[mf] + du;
                abase[mf] = As_u + (uint32_t)q * 128;
                axsh[mf]  = (uint32_t)(q & 7) << 4;
            }
            uint32_t bb = b_base + (uint32_t)buf * BBYTES;
#pragma unroll
            for (int kk = 0; kk < 4; kk++) {
                uint32_t koff = ((uint32_t)(kk * 2 + jBh)) << 4;
                uint32_t bf0[4], bf1[4];
                ldsm_x4(bf0, bb +        (koff ^ xorB_sh));          // co n_w*32 +  0..15
                ldsm_x4(bf1, bb + 2048 + (koff ^ xorB_sh));          // co n_w*32 + 16..31
                uint32_t koffA = ((uint32_t)(kk * 2 + jAh)) << 4;
#pragma unroll
                for (int mf = 0; mf < 4; mf++) {
                    uint32_t af[4];
                    ldsm_x4(af, abase[mf] + (koffA ^ axsh[mf]));
                    mma_tf32(acc[mf][0], af, bf0);
                    mma_tf32(acc[mf][1], af, bf0 + 2);
                    mma_tf32(acc[mf][2], af, bf1);
                    mma_tf32(acc[mf][3], af, bf1 + 2);
                }
            }
            buf ^= 1;
        }
    }

    // ---- epilogue: direct NCHW stores (flattened pixel index = p) ----
    float* ob = out + (size_t)b * CO_ * HW;
    int g = lid >> 2, tg = lid & 3;
#pragma unroll
    for (int mf = 0; mf < 4; mf++) {
#pragma unroll
        for (int h = 0; h < 2; h++) {
            int p = p0 + (m_w * 4 + mf) * 16 + g + 8 * h;
            if (p < HW) {
#pragma unroll
                for (int nn = 0; nn < 4; nn++) {
                    int col = n_w * 32 + nn * 8 + (tg << 1);
                    ob[(size_t)col * HW + p]       = acc[mf][nn][2 * h];
                    ob[(size_t)(col + 1) * HW + p] = acc[mf][nn][2 * h + 1];
                }
            }
        }
    }
}

// ---------------------------------------------------------------------------
extern "C" void kernel_launch(void* const* d_in, const int* in_sizes, int n_in,
                              void* d_out, int out_size) {
    const float* input = (const float*)d_in[0];   // [32,128,56,56]
    const float* eps   = (const float*)d_in[1];   // [32,128,128,3,3]
    const float* psi   = (const float*)d_in[2];   // [128,128,3,3]
    const float* mu    = (const float*)d_in[3];   // [128,128,3,3]
    float* out = (float*)d_out;                   // [32,128,56,56]

    prepw_kernel<<<dim3(CO_, BB), 128>>>(eps, psi, mu);
    zeroborder_kernel<<<(BB * 344 * 32 + 255) / 256, 256>>>();
    intrans_kernel<<<dim3(98, 4, BB), dim3(32, 8)>>>(input);

    cudaFuncSetAttribute(conv_mma, cudaFuncAttributeMaxDynamicSharedMemorySize, SMEM_CONV);
    conv_mma<<<dim3(NTILES, BB), 256, SMEM_CONV>>>(out);
}